// round 11
// baseline (speedup 1.0000x reference)
#include <cuda_runtime.h>
#include <cstdint>

// Problem constants
#define NN 16      // N (both u and v)
#define CC 4       // C
#define HH 32
#define WW 32
#define SS 1024    // H*W
#define K2 9       // 3x3
#define EE 144     // C*C*K2 floats per (u,v,s) chunk
#define ST 16      // s-values per block = half an image row
#define NLANES 36  // EE/4 quads
#define NSGRP 8    // s-groups (each handles 2 s)
#define NTHREADS (NSGRP * NLANES)  // 288
#define NSTAGE 4   // weight pipeline depth

#define STAGE_BYTES (ST * EE * 4)              // 9216
// x smem tile: [u(16)][c(4)][row(3)][col(20: j=0..17 used = gcols w0-1..w0+16)]
#define XS_FLOATS (NN * CC * 3 * 20)           // 3840
#define SMEM_W 0                               // 4 weight stages (36864 B)
#define SMEM_XS (NSTAGE * STAGE_BYTES)         // 36864
#define SMEM_CM (SMEM_XS + XS_FLOATS * 4)      // 52224: cm [16 u][16 co]
#define SMEM_MBAR (SMEM_CM + 1024)             // 53248: full[4]
#define SMEM_TOTAL (SMEM_MBAR + 64)            // 53312

__device__ __forceinline__ unsigned smem_u32(const void* p) {
    unsigned a;
    asm("{ .reg .u64 t; cvta.to.shared.u64 t, %1; cvt.u32.u64 %0, t; }"
        : "=r"(a) : "l"(p));
    return a;
}

// ---- mbarrier helpers ----
__device__ __forceinline__ void mbar_init(unsigned mb, unsigned count) {
    asm volatile("mbarrier.init.shared.b64 [%0], %1;" :: "r"(mb), "r"(count) : "memory");
}
__device__ __forceinline__ void mbar_expect_tx(unsigned mb, unsigned bytes) {
    asm volatile("mbarrier.arrive.expect_tx.shared.b64 _, [%0], %1;"
                 :: "r"(mb), "r"(bytes) : "memory");
}
__device__ __forceinline__ void mbar_wait(unsigned mb, unsigned parity) {
    unsigned done;
    asm volatile(
        "{\n\t.reg .pred p;\n\t"
        "mbarrier.try_wait.parity.acquire.cta.shared::cta.b64 p, [%1], %2;\n\t"
        "selp.b32 %0, 1, 0, p;\n\t}"
        : "=r"(done) : "r"(mb), "r"(parity) : "memory");
    if (!done) {
        asm volatile(
            "{\n\t.reg .pred P1;\n\t"
            "W_%=:\n\t"
            "mbarrier.try_wait.parity.acquire.cta.shared::cta.b64 P1, [%0], %1, 0x989680;\n\t"
            "@P1 bra.uni D_%=;\n\t"
            "bra.uni W_%=;\n\t"
            "D_%=:\n\t}"
            :: "r"(mb), "r"(parity) : "memory");
    }
}
__device__ __forceinline__ void bulk_copy(unsigned dst_smem, const void* src,
                                          unsigned bytes, unsigned mb) {
    asm volatile(
        "cp.async.bulk.shared::cta.global.mbarrier::complete_tx::bytes [%0], [%1], %2, [%3];"
        :: "r"(dst_smem), "l"(src), "r"(bytes), "r"(mb) : "memory");
}

__global__ __launch_bounds__(NTHREADS, 4)
void plastic_edges_kernel(const float* __restrict__ x,
                          const float* __restrict__ weight,
                          const float* __restrict__ chan_map,
                          const float* __restrict__ mask,
                          float* __restrict__ out) {
    extern __shared__ __align__(128) char smem[];
    float* xs    = (float*)(smem + SMEM_XS);   // [u][c][3][20]
    float* cm_sh = (float*)(smem + SMEM_CM);   // [16 u][16 co]
    const unsigned sbase = smem_u32(smem);
    const unsigned mbF = sbase + SMEM_MBAR;    // full[4]

    const int t    = threadIdx.x;
    const int bx   = blockIdx.x;           // 0..63
    const int h    = bx >> 1;
    const int w0   = (bx & 1) << 4;
    const int bs0  = h * 32 + w0;          // s tile base
    const int v    = blockIdx.y;           // one v per block
    const int sgrp = t / NLANES;           // 0..7
    const int lane = t % NLANES;           // 0..35 (quad index)
    // staggered u start: spread the instantaneous DRAM footprint over all slabs
    const int u0   = (bx + v) & 15;

    // ---- mbarriers ----
    if (t == 0) {
#pragma unroll
        for (int s = 0; s < NSTAGE; s++) mbar_init(mbF + 8 * s, 1);
    }
    // ---- stage cm_sh[u][c*4+o] ----
    if (t < 256) {
        int u  = t >> 4;
        int co = t & 15;
        int uv = u * NN + v;
        cm_sh[t] = chan_map[uv * 16 + co] * mask[uv];
    }
    __syncthreads();   // mbarrier init visible before TMA arms

    const float* wsrc0 = weight + ((size_t)v * SS + bs0) * EE;  // + u*NN*SS*EE
    const size_t wstride = (size_t)NN * SS * EE;

    // prologue: arm + fill slots for steps 0..3 (chunks u0..u0+3 mod 16)
    if (t == 0) {
#pragma unroll
        for (int s = 0; s < NSTAGE; s++) {
            int uc = (u0 + s) & 15;
            mbar_expect_tx(mbF + 8 * s, STAGE_BYTES);
            bulk_copy(sbase + SMEM_W + s * STAGE_BYTES,
                      wsrc0 + (size_t)uc * wstride, STAGE_BYTES, mbF + 8 * s);
        }
    }

    // ---- stage raw x rows into xs (overlaps with TMA fills) ----
    for (int i = t; i < XS_FLOATS; i += NTHREADS) xs[i] = 0.0f;
    __syncthreads();
    for (int i = t; i < NN * CC * 3 * 18; i += NTHREADS) {
        int j  = i % 18;                   // local col 0..17 -> gcol w0-1+j
        int rr = (i / 18) % 3;             // rows h-1..h+1
        int uc = i / 54;                   // u*4 + c
        int r  = h + rr - 1;
        int gc = w0 - 1 + j;
        if ((unsigned)r < 32u && (unsigned)gc < 32u)
            xs[(uc * 3 + rr) * 20 + j] = x[(uc * 32 + r) * 32 + gc];
    }

    // per-thread static decode for quad p = lane*4 + e
    // x value for (p, sl): xs[u][c][ki][ sl + kj ]   (sl = local s = local w)
    int cmi[4];        // cm index c*4+o
    unsigned xoff[4];  // byte offset within a u-slab, excluding sl
    {
        int p0 = lane * 4;
        int c  = p0 / 36;                  // constant across the quad
#pragma unroll
        for (int e = 0; e < 4; e++) {
            int p  = p0 + e;
            int o  = (p % 36) / 9;
            int k  = p % 9;
            int ki = k / 3, kj = k % 3;
            cmi[e]  = c * 4 + o;
            xoff[e] = ((unsigned)((c * 3 + ki) * 20 + kj)) * 4u;
        }
    }
    const unsigned xb = sbase + SMEM_XS;   // u stride = 4*3*20*4 = 960 B

    float acc[2][4];
#pragma unroll
    for (int i = 0; i < 2; i++)
#pragma unroll
        for (int e = 0; e < 4; e++) acc[i][e] = 0.0f;

    const unsigned wthr = (unsigned)(sgrp * 2) * (EE * 4) + (unsigned)lane * 16;
    const unsigned sl0  = (unsigned)(sgrp * 2);

    __syncthreads();   // xs fully staged

    for (int step = 0; step < NN; step++) {
        const int u    = (u0 + step) & 15;
        const int slot = step & (NSTAGE - 1);
        const unsigned par = (step >> 2) & 1;

        // ---- operand prep BEFORE the wait: cm, x, and xc = x*cm ----
        const unsigned xu = xb + (unsigned)u * 960u;
        float xc[4][2];
#pragma unroll
        for (int e = 0; e < 4; e++) {
            float cmv = cm_sh[u * 16 + cmi[e]];
            float xv0, xv1;
            asm volatile("ld.shared.f32 %0, [%1];"
                : "=f"(xv0) : "r"(xu + xoff[e] + sl0 * 4u));
            asm volatile("ld.shared.f32 %0, [%1];"
                : "=f"(xv1) : "r"(xu + xoff[e] + sl0 * 4u + 4u));
            xc[e][0] = xv0 * cmv;
            xc[e][1] = xv1 * cmv;
        }

        mbar_wait(mbF + 8 * slot, par);

        // ---- post-wait critical path: 2x (LDS.128 + 4 FFMA) ----
        const unsigned sw = sbase + SMEM_W + slot * STAGE_BYTES + wthr;
#pragma unroll
        for (int i = 0; i < 2; i++) {
            float w0v, w1v, w2v, w3v;
            asm volatile("ld.shared.v4.f32 {%0,%1,%2,%3}, [%4];"
                : "=f"(w0v), "=f"(w1v), "=f"(w2v), "=f"(w3v)
                : "r"(sw + i * (EE * 4)));
            acc[i][0] = fmaf(w0v, xc[0][i], acc[i][0]);
            acc[i][1] = fmaf(w1v, xc[1][i], acc[i][1]);
            acc[i][2] = fmaf(w2v, xc[2][i], acc[i][2]);
            acc[i][3] = fmaf(w3v, xc[3][i], acc[i][3]);
        }
        __syncthreads();   // all reads of this slot done (proven-safe release)
        if (t == 0 && step + NSTAGE < NN) {
            int un = (u0 + step + NSTAGE) & 15;
            mbar_expect_tx(mbF + 8 * slot, STAGE_BYTES);
            bulk_copy(sbase + SMEM_W + slot * STAGE_BYTES,
                      wsrc0 + (size_t)un * wstride, STAGE_BYTES,
                      mbF + 8 * slot);
        }
    }

    // ---- c-reduction via shared (reuse stage-0 buffer), fused fold scatter ----
    // no copies in flight after the loop (last refill consumed at step 15)
    float* red = (float*)smem;   // [16 s][144] = 9216 B
#pragma unroll
    for (int i = 0; i < 2; i++) {
        float4 pk = make_float4(acc[i][0], acc[i][1], acc[i][2], acc[i][3]);
        *(float4*)&red[(sgrp * 2 + i) * EE + lane * 4] = pk;
    }
    __syncthreads();

    // 16*36 = 576 (s, o*9+k) outputs; sum 4 c-slices each; fold-scatter
    for (int r = t; r < ST * 36; r += NTHREADS) {
        int sl = r / 36;
        int ok = r % 36;             // o*9 + k
        int o  = ok / 9, k = ok % 9;
        const float* rb = &red[sl * EE + ok];
        float val = rb[0] + rb[36] + rb[72] + rb[108];
        // fold: channel index ch = k*C + o decoded as (cf, fi, fj)
        int ch  = k * CC + o;
        int cf  = ch / 9;
        int rem = ch % 9;
        int fi  = rem / 3, fj = rem % 3;
        int s = bs0 + sl;
        int hh = s >> 5, w = s & 31;
        int y = hh + fi - 1, xx = w + fj - 1;
        if ((unsigned)y < 32u && (unsigned)xx < 32u)
            atomicAdd(&out[((v * CC + cf) * HH + y) * WW + xx], val);
    }
}

extern "C" void kernel_launch(void* const* d_in, const int* in_sizes, int n_in,
                              void* d_out, int out_size) {
    // identify inputs by element count (robust to ordering)
    const float *x = nullptr, *wt = nullptr, *cm = nullptr, *mk = nullptr;
    for (int i = 0; i < n_in; i++) {
        switch (in_sizes[i]) {
            case NN * CC * HH * WW:           x  = (const float*)d_in[i]; break; // 65536
            case NN * NN * SS * CC * CC * K2: wt = (const float*)d_in[i]; break; // 37748736
            case NN * NN * CC * CC:           cm = (const float*)d_in[i]; break; // 4096
            case NN * NN:                     mk = (const float*)d_in[i]; break; // 256
            default: break;
        }
    }
    float* out = (float*)d_out;

    cudaFuncSetAttribute(plastic_edges_kernel,
                         cudaFuncAttributeMaxDynamicSharedMemorySize, SMEM_TOTAL);

    cudaMemsetAsync(out, 0, (size_t)out_size * sizeof(float), 0);

    dim3 grid(SS / ST, NN);                  // (64, 16) = 1024 blocks
    plastic_edges_kernel<<<grid, NTHREADS, SMEM_TOTAL, 0>>>(x, wt, cm, mk, out);
}